// round 11
// baseline (speedup 1.0000x reference)
#include <cuda_runtime.h>
#include <cstdint>

#define MT 128
#define NT 256
#define K_DIM 8192
#define N_DIM 512
#define CHUNKS (K_DIM / 32)
#define THREADS 512

#define SM_BIAS   0
#define SM_TILES  1024
#define A_OFF     0
#define B_OFF     (MT * 128)                 // 16384
#define STAGE_BYTES ((MT + NT) * 128)        // 49152
#define SMEM_TOTAL (SM_TILES + 4 * STAGE_BYTES)  // 197632

// pre-gathered, tf32-rounded virtual weight [512][8192]
__device__ float g_wfull[(size_t)N_DIM * K_DIM];

// ---------------- helpers ----------------
__device__ __forceinline__ uint32_t smem_u32(const void* p) {
    uint32_t a;
    asm("{ .reg .u64 t; cvta.to.shared.u64 t, %1; cvt.u32.u64 %0, t; }" : "=r"(a) : "l"(p));
    return a;
}
__device__ __forceinline__ uint32_t swz(uint32_t o) { return o ^ ((o >> 3) & 0x70); }

__device__ __forceinline__ void cp16(uint32_t dst, const void* src) {
    asm volatile("cp.async.cg.shared.global [%0], [%1], 16;" :: "r"(dst), "l"(src) : "memory");
}

// swizzled shared read: row = 128B rows, w = 32-bit word index 0..31
__device__ __forceinline__ float lds_sw(const char* base, int row, int w) {
    return *(const float*)(base + row * 128 + (((uint32_t)w ^ (((uint32_t)row & 7u) << 2)) << 2));
}

__device__ __forceinline__ void mma8(float* c, const float* a, const float* b) {
    asm volatile(
        "mma.sync.aligned.m16n8k8.row.col.f32.tf32.tf32.f32 "
        "{%0,%1,%2,%3}, {%4,%5,%6,%7}, {%8,%9}, {%0,%1,%2,%3};"
        : "+f"(c[0]), "+f"(c[1]), "+f"(c[2]), "+f"(c[3])
        : "r"(__float_as_uint(a[0])), "r"(__float_as_uint(a[1])),
          "r"(__float_as_uint(a[2])), "r"(__float_as_uint(a[3])),
          "r"(__float_as_uint(b[0])), "r"(__float_as_uint(b[1])));
}

// ---------------- pre-gather: w_full[n][k] = rna_tf32(weight[n][h(n/32,k/32)*32 + k%32])
__global__ void gather_w(const float* __restrict__ w, const int* __restrict__ rn) {
    const uint32_t r0 = (uint32_t)rn[0], r1 = (uint32_t)rn[1],
                   r2 = (uint32_t)rn[2], r3 = (uint32_t)rn[3];
    int gid = blockIdx.x * 256 + threadIdx.x;     // [0, 512*8192/4)
    int n = gid >> 11;                            // / 2048
    int k = (gid & 2047) << 2;
    uint32_t kb = (uint32_t)(k >> 5), nb = (uint32_t)(n >> 5);
    uint32_t h = ((kb * r0 + nb * r1 + r2) ^ r3) % 32u;
    const float4 v = *(const float4*)(w + n * 1024 + h * 32u + (k & 31));
    uint4 o;
    asm("cvt.rna.tf32.f32 %0, %1;" : "=r"(o.x) : "f"(v.x));
    asm("cvt.rna.tf32.f32 %0, %1;" : "=r"(o.y) : "f"(v.y));
    asm("cvt.rna.tf32.f32 %0, %1;" : "=r"(o.z) : "f"(v.z));
    asm("cvt.rna.tf32.f32 %0, %1;" : "=r"(o.w) : "f"(v.w));
    *(uint4*)(g_wfull + (size_t)n * K_DIM + k) = o;
}

// ---------------- main GEMM ----------------
__global__ void __launch_bounds__(THREADS, 1)
ssl_gemm(const float* __restrict__ x, const float* __restrict__ bias, float* __restrict__ out) {
    extern __shared__ char smem[];
    const uint32_t sb = smem_u32(smem);
    const int tid = threadIdx.x;
    const int lane = tid & 31, wid = tid >> 5;
    const int wm = (wid & 1) * 64;       // warp m offset (2 warp-rows of 64)
    const int wn = (wid >> 1) * 32;      // warp n offset (8 warp-cols of 32)
    const int g = lane >> 2, t = lane & 3;
    const int m0 = blockIdx.y * MT, n0 = blockIdx.x * NT;

    if (tid < 128)
        ((float2*)(smem + SM_BIAS))[tid] = ((const float2*)(bias + n0))[tid];

    float acc[4][4][4];
    #pragma unroll
    for (int i = 0; i < 4; i++)
        #pragma unroll
        for (int j = 0; j < 4; j++)
            #pragma unroll
            for (int q = 0; q < 4; q++) acc[i][j][q] = 0.f;

    const float* aP = x + (size_t)m0 * K_DIM;
    const float* bP = g_wfull + (size_t)n0 * K_DIM;

    // issue cp.async for one 32-wide K chunk into stage (kc & 3)
    auto load_chunk = [&](int kc) {
        const uint32_t base = sb + SM_TILES + (uint32_t)(kc & 3) * STAGE_BYTES;
        const int k0 = kc * 32;
        #pragma unroll
        for (int j = 0; j < 2; j++) {       // A: 128 rows x 8 x 16B = 1024 ops
            int i = j * THREADS + tid, row = i >> 3, c = i & 7;
            cp16(base + A_OFF + swz((uint32_t)(row * 128 + c * 16)),
                 aP + (size_t)row * K_DIM + k0 + c * 4);
        }
        #pragma unroll
        for (int j = 0; j < 4; j++) {       // B: 256 rows x 8 x 16B = 2048 ops
            int i = j * THREADS + tid, row = i >> 3, c = i & 7;
            cp16(base + B_OFF + swz((uint32_t)(row * 128 + c * 16)),
                 bP + (size_t)row * K_DIM + k0 + c * 4);
        }
    };

    load_chunk(0); asm volatile("cp.async.commit_group;" ::: "memory");
    load_chunk(1); asm volatile("cp.async.commit_group;" ::: "memory");
    load_chunk(2); asm volatile("cp.async.commit_group;" ::: "memory");

    #pragma unroll 1
    for (int kc = 0; kc < CHUNKS; kc++) {
        // my groups for stage kc are done; barrier publishes data CTA-wide and
        // orders everyone's compute(kc-1) before the overwrite of its buffer below
        asm volatile("cp.async.wait_group 2;" ::: "memory");
        __syncthreads();
        if (kc + 3 < CHUNKS) load_chunk(kc + 3);
        asm volatile("cp.async.commit_group;" ::: "memory");

        const char* sA = smem + SM_TILES + (kc & 3) * STAGE_BYTES + A_OFF;
        const char* sB = smem + SM_TILES + (kc & 3) * STAGE_BYTES + B_OFF;
        #pragma unroll
        for (int ks = 0; ks < 4; ks++) {
            const int k0 = ks * 8;
            float af[4][4], bf[4][2];
            #pragma unroll
            for (int mi = 0; mi < 4; mi++) {
                int r = wm + mi * 16 + g;
                af[mi][0] = lds_sw(sA, r,     k0 + t);
                af[mi][1] = lds_sw(sA, r + 8, k0 + t);
                af[mi][2] = lds_sw(sA, r,     k0 + t + 4);
                af[mi][3] = lds_sw(sA, r + 8, k0 + t + 4);
            }
            #pragma unroll
            for (int ni = 0; ni < 4; ni++) {
                int n = wn + ni * 8 + g;
                bf[ni][0] = lds_sw(sB, n, k0 + t);
                bf[ni][1] = lds_sw(sB, n, k0 + t + 4);
            }
            #pragma unroll
            for (int mi = 0; mi < 4; mi++)
                #pragma unroll
                for (int ni = 0; ni < 4; ni++)
                    mma8(acc[mi][ni], af[mi], bf[ni]);
        }
    }

    // epilogue: bias + store
    const float* bs = (const float*)(smem + SM_BIAS);
    #pragma unroll
    for (int mi = 0; mi < 4; mi++) {
        const int r0 = m0 + wm + mi * 16 + g;
        #pragma unroll
        for (int ni = 0; ni < 4; ni++) {
            const int col = wn + ni * 8 + 2 * t;
            float2 v0, v1;
            v0.x = acc[mi][ni][0] + bs[col];
            v0.y = acc[mi][ni][1] + bs[col + 1];
            v1.x = acc[mi][ni][2] + bs[col];
            v1.y = acc[mi][ni][3] + bs[col + 1];
            *(float2*)(out + (size_t)r0 * N_DIM + n0 + col) = v0;
            *(float2*)(out + (size_t)(r0 + 8) * N_DIM + n0 + col) = v1;
        }
    }
}

extern "C" void kernel_launch(void* const* d_in, const int* in_sizes, int n_in,
                              void* d_out, int out_size) {
    (void)in_sizes; (void)n_in; (void)out_size;
    const float* x    = (const float*)d_in[0];
    const float* w    = (const float*)d_in[1];
    const float* bias = (const float*)d_in[2];
    const int*   rn   = (const int*)d_in[3];
    float* out = (float*)d_out;

    gather_w<<<(N_DIM * K_DIM / 4) / 256, 256>>>(w, rn);

    cudaFuncSetAttribute(ssl_gemm, cudaFuncAttributeMaxDynamicSharedMemorySize, SMEM_TOTAL);
    ssl_gemm<<<dim3(N_DIM / NT, 8192 / MT), THREADS, SMEM_TOTAL>>>(x, bias, out);
}

// round 12
// speedup vs baseline: 1.6857x; 1.6857x over previous
#include <cuda_runtime.h>
#include <cstdint>

#define MT 128
#define NT 256
#define K_DIM 8192
#define N_DIM 512
#define CHUNKS (K_DIM / 32)
#define THREADS 256

#define SM_BIAS   0
#define SM_TILES  1024
#define A_OFF     0
#define B_OFF     (MT * 128)                 // 16384
#define STAGE_BYTES ((MT + NT) * 128)        // 49152
#define SMEM_TOTAL (SM_TILES + 4 * STAGE_BYTES)  // 197632

// pre-gathered, tf32-rounded virtual weight [512][8192]
__device__ float g_wfull[(size_t)N_DIM * K_DIM];

// ---------------- helpers ----------------
__device__ __forceinline__ uint32_t smem_u32(const void* p) {
    uint32_t a;
    asm("{ .reg .u64 t; cvta.to.shared.u64 t, %1; cvt.u32.u64 %0, t; }" : "=r"(a) : "l"(p));
    return a;
}
__device__ __forceinline__ uint32_t swz(uint32_t o) { return o ^ ((o >> 3) & 0x70); }

__device__ __forceinline__ void cp16(uint32_t dst, const void* src) {
    asm volatile("cp.async.cg.shared.global [%0], [%1], 16;" :: "r"(dst), "l"(src) : "memory");
}

// ldmatrix x4: four 8x8 b16 tiles; tf32-compatible (bit-pattern agnostic)
__device__ __forceinline__ void ldsm4(uint32_t* r, uint32_t addr) {
    asm volatile("ldmatrix.sync.aligned.m8n8.x4.shared.b16 {%0,%1,%2,%3}, [%4];"
                 : "=r"(r[0]), "=r"(r[1]), "=r"(r[2]), "=r"(r[3]) : "r"(addr));
}

__device__ __forceinline__ void mma8(float* c, const uint32_t* a, const uint32_t* b) {
    asm volatile(
        "mma.sync.aligned.m16n8k8.row.col.f32.tf32.tf32.f32 "
        "{%0,%1,%2,%3}, {%4,%5,%6,%7}, {%8,%9}, {%0,%1,%2,%3};"
        : "+f"(c[0]), "+f"(c[1]), "+f"(c[2]), "+f"(c[3])
        : "r"(a[0]), "r"(a[1]), "r"(a[2]), "r"(a[3]), "r"(b[0]), "r"(b[1]));
}

// ---------------- pre-gather: w_full[n][k] = rna_tf32(weight[n][h(n/32,k/32)*32 + k%32])
__global__ void gather_w(const float* __restrict__ w, const int* __restrict__ rn) {
    const uint32_t r0 = (uint32_t)rn[0], r1 = (uint32_t)rn[1],
                   r2 = (uint32_t)rn[2], r3 = (uint32_t)rn[3];
    int gid = blockIdx.x * 256 + threadIdx.x;     // [0, 512*8192/4)
    int n = gid >> 11;                            // / 2048
    int k = (gid & 2047) << 2;
    uint32_t kb = (uint32_t)(k >> 5), nb = (uint32_t)(n >> 5);
    uint32_t h = ((kb * r0 + nb * r1 + r2) ^ r3) % 32u;
    const float4 v = *(const float4*)(w + n * 1024 + h * 32u + (k & 31));
    uint4 o;
    asm("cvt.rna.tf32.f32 %0, %1;" : "=r"(o.x) : "f"(v.x));
    asm("cvt.rna.tf32.f32 %0, %1;" : "=r"(o.y) : "f"(v.y));
    asm("cvt.rna.tf32.f32 %0, %1;" : "=r"(o.z) : "f"(v.z));
    asm("cvt.rna.tf32.f32 %0, %1;" : "=r"(o.w) : "f"(v.w));
    *(uint4*)(g_wfull + (size_t)n * K_DIM + k) = o;
}

// ---------------- main GEMM ----------------
__global__ void __launch_bounds__(THREADS, 1)
ssl_gemm(const float* __restrict__ x, const float* __restrict__ bias, float* __restrict__ out) {
    extern __shared__ char smem[];
    const uint32_t sb = smem_u32(smem);
    const int tid = threadIdx.x;
    const int lane = tid & 31, wid = tid >> 5;
    const int wm = (wid & 1) * 64;       // warp m offset (2 x 64)
    const int wn = (wid >> 1) * 64;      // warp n offset (4 x 64)
    const int g = lane >> 2, t = lane & 3;
    const int m0 = blockIdx.y * MT, n0 = blockIdx.x * NT;

    // per-thread ldmatrix row/byte selectors
    // A x4: lanes 0-7 -> rows 0-7 k-lo, 8-15 -> rows 8-15 k-lo, 16-23 -> rows 0-7 k-hi, 24-31 -> rows 8-15 k-hi
    const int a_row = lane & 15;
    const int a_kb  = (lane >> 4) << 4;          // 0 or 16 bytes
    // B x4 (two 8-row n-tiles): lanes 0-7 -> ni rows k-lo, 8-15 -> ni rows k-hi,
    //                           16-23 -> ni+1 rows k-lo, 24-31 -> ni+1 rows k-hi
    const int b_row = (lane & 7) + ((lane >> 4) << 3);
    const int b_kb  = ((lane >> 3) & 1) << 4;

    if (tid < 128)
        ((float2*)(smem + SM_BIAS))[tid] = ((const float2*)(bias + n0))[tid];

    float acc[4][8][4];
    #pragma unroll
    for (int i = 0; i < 4; i++)
        #pragma unroll
        for (int j = 0; j < 8; j++)
            #pragma unroll
            for (int q = 0; q < 4; q++) acc[i][j][q] = 0.f;

    const float* aP = x + (size_t)m0 * K_DIM;
    const float* bP = g_wfull + (size_t)n0 * K_DIM;

    auto load_chunk = [&](int kc) {
        const uint32_t base = sb + SM_TILES + (uint32_t)(kc & 3) * STAGE_BYTES;
        const int k0 = kc * 32;
        #pragma unroll
        for (int j = 0; j < 4; j++) {       // A: 128 rows x 8 x 16B
            int i = j * THREADS + tid, row = i >> 3, c = i & 7;
            cp16(base + A_OFF + swz((uint32_t)(row * 128 + c * 16)),
                 aP + (size_t)row * K_DIM + k0 + c * 4);
        }
        #pragma unroll
        for (int j = 0; j < 8; j++) {       // B: 256 rows x 8 x 16B
            int i = j * THREADS + tid, row = i >> 3, c = i & 7;
            cp16(base + B_OFF + swz((uint32_t)(row * 128 + c * 16)),
                 bP + (size_t)row * K_DIM + k0 + c * 4);
        }
    };

    load_chunk(0); asm volatile("cp.async.commit_group;" ::: "memory");
    load_chunk(1); asm volatile("cp.async.commit_group;" ::: "memory");
    load_chunk(2); asm volatile("cp.async.commit_group;" ::: "memory");

    #pragma unroll 1
    for (int kc = 0; kc < CHUNKS; kc++) {
        asm volatile("cp.async.wait_group 2;" ::: "memory");
        __syncthreads();   // publishes chunk kc data; orders compute(kc-1) before overwrite below
        if (kc + 3 < CHUNKS) load_chunk(kc + 3);
        asm volatile("cp.async.commit_group;" ::: "memory");

        const uint32_t sA = sb + SM_TILES + (uint32_t)(kc & 3) * STAGE_BYTES + A_OFF;
        const uint32_t sB = sA + B_OFF;
        #pragma unroll
        for (int ks = 0; ks < 4; ks++) {
            const int kbyte = ks * 32;
            uint32_t af[4][4], bf[4][4];
            #pragma unroll
            for (int mi = 0; mi < 4; mi++)
                ldsm4(af[mi], sA + swz((uint32_t)((wm + mi * 16 + a_row) * 128 + kbyte + a_kb)));
            #pragma unroll
            for (int np = 0; np < 4; np++)   // covers n-tiles 2*np, 2*np+1
                ldsm4(bf[np], sB + swz((uint32_t)((wn + np * 16 + b_row) * 128 + kbyte + b_kb)));
            #pragma unroll
            for (int mi = 0; mi < 4; mi++)
                #pragma unroll
                for (int np = 0; np < 4; np++) {
                    mma8(acc[mi][2 * np],     af[mi], &bf[np][0]);
                    mma8(acc[mi][2 * np + 1], af[mi], &bf[np][2]);
                }
        }
    }

    // epilogue: bias + store
    const float* bs = (const float*)(smem + SM_BIAS);
    #pragma unroll
    for (int mi = 0; mi < 4; mi++) {
        const int r0 = m0 + wm + mi * 16 + g;
        #pragma unroll
        for (int ni = 0; ni < 8; ni++) {
            const int col = wn + ni * 8 + 2 * t;
            float2 v0, v1;
            v0.x = acc[mi][ni][0] + bs[col];
            v0.y = acc[mi][ni][1] + bs[col + 1];
            v1.x = acc[mi][ni][2] + bs[col];
            v1.y = acc[mi][ni][3] + bs[col + 1];
            *(float2*)(out + (size_t)r0 * N_DIM + n0 + col) = v0;
            *(float2*)(out + (size_t)(r0 + 8) * N_DIM + n0 + col) = v1;
        }
    }
}

extern "C" void kernel_launch(void* const* d_in, const int* in_sizes, int n_in,
                              void* d_out, int out_size) {
    (void)in_sizes; (void)n_in; (void)out_size;
    const float* x    = (const float*)d_in[0];
    const float* w    = (const float*)d_in[1];
    const float* bias = (const float*)d_in[2];
    const int*   rn   = (const int*)d_in[3];
    float* out = (float*)d_out;

    gather_w<<<(N_DIM * K_DIM / 4) / 256, 256>>>(w, rn);

    cudaFuncSetAttribute(ssl_gemm, cudaFuncAttributeMaxDynamicSharedMemorySize, SMEM_TOTAL);
    ssl_gemm<<<dim3(N_DIM / NT, 8192 / MT), THREADS, SMEM_TOTAL>>>(x, bias, out);
}

// round 13
// speedup vs baseline: 1.7051x; 1.0115x over previous
#include <cuda_runtime.h>
#include <cstdint>

#define MT 128
#define NT 128
#define K_DIM 8192
#define N_DIM 512
#define CHUNKS (K_DIM / 32)
#define THREADS 256
#define STAGES 3

#define SM_BIAS   0
#define SM_TILES  1024
#define A_OFF     0
#define B_OFF     (MT * 128)                 // 16384
#define STAGE_BYTES ((MT + NT) * 128)        // 32768
#define SMEM_TOTAL (SM_TILES + STAGES * STAGE_BYTES)  // 99328 -> 2 CTAs/SM

// pre-gathered, tf32-rounded virtual weight [512][8192]
__device__ float g_wfull[(size_t)N_DIM * K_DIM];

// ---------------- helpers ----------------
__device__ __forceinline__ uint32_t smem_u32(const void* p) {
    uint32_t a;
    asm("{ .reg .u64 t; cvta.to.shared.u64 t, %1; cvt.u32.u64 %0, t; }" : "=r"(a) : "l"(p));
    return a;
}
__device__ __forceinline__ uint32_t swz(uint32_t o) { return o ^ ((o >> 3) & 0x70); }

__device__ __forceinline__ void cp16(uint32_t dst, const void* src) {
    asm volatile("cp.async.cg.shared.global [%0], [%1], 16;" :: "r"(dst), "l"(src) : "memory");
}

// ldmatrix x4: four 8x8 b16 tiles; tf32-compatible (bit-pattern agnostic)
__device__ __forceinline__ void ldsm4(uint32_t* r, uint32_t addr) {
    asm volatile("ldmatrix.sync.aligned.m8n8.x4.shared.b16 {%0,%1,%2,%3}, [%4];"
                 : "=r"(r[0]), "=r"(r[1]), "=r"(r[2]), "=r"(r[3]) : "r"(addr));
}

__device__ __forceinline__ void mma8(float* c, const uint32_t* a, const uint32_t* b) {
    asm volatile(
        "mma.sync.aligned.m16n8k8.row.col.f32.tf32.tf32.f32 "
        "{%0,%1,%2,%3}, {%4,%5,%6,%7}, {%8,%9}, {%0,%1,%2,%3};"
        : "+f"(c[0]), "+f"(c[1]), "+f"(c[2]), "+f"(c[3])
        : "r"(a[0]), "r"(a[1]), "r"(a[2]), "r"(a[3]), "r"(b[0]), "r"(b[1]));
}

// ---------------- pre-gather: w_full[n][k] = rna_tf32(weight[n][h(n/32,k/32)*32 + k%32])
__global__ void gather_w(const float* __restrict__ w, const int* __restrict__ rn) {
    const uint32_t r0 = (uint32_t)rn[0], r1 = (uint32_t)rn[1],
                   r2 = (uint32_t)rn[2], r3 = (uint32_t)rn[3];
    int gid = blockIdx.x * 256 + threadIdx.x;     // [0, 512*8192/4)
    int n = gid >> 11;                            // / 2048
    int k = (gid & 2047) << 2;
    uint32_t kb = (uint32_t)(k >> 5), nb = (uint32_t)(n >> 5);
    uint32_t h = ((kb * r0 + nb * r1 + r2) ^ r3) % 32u;
    const float4 v = *(const float4*)(w + n * 1024 + h * 32u + (k & 31));
    uint4 o;
    asm("cvt.rna.tf32.f32 %0, %1;" : "=r"(o.x) : "f"(v.x));
    asm("cvt.rna.tf32.f32 %0, %1;" : "=r"(o.y) : "f"(v.y));
    asm("cvt.rna.tf32.f32 %0, %1;" : "=r"(o.z) : "f"(v.z));
    asm("cvt.rna.tf32.f32 %0, %1;" : "=r"(o.w) : "f"(v.w));
    *(uint4*)(g_wfull + (size_t)n * K_DIM + k) = o;
}

// ---------------- main GEMM ----------------
__global__ void __launch_bounds__(THREADS, 2)
ssl_gemm(const float* __restrict__ x, const float* __restrict__ bias, float* __restrict__ out) {
    extern __shared__ char smem[];
    const uint32_t sb = smem_u32(smem);
    const int tid = threadIdx.x;
    const int lane = tid & 31, wid = tid >> 5;
    const int wm = (wid & 1) * 64;       // 2 warp-rows of 64
    const int wn = (wid >> 1) * 32;      // 4 warp-cols of 32
    const int g = lane >> 2, t = lane & 3;
    const int m0 = blockIdx.y * MT, n0 = blockIdx.x * NT;

    // ldmatrix per-thread selectors
    const int a_row = lane & 15;                 // A x4: 16 rows x 32B (k-lo/k-hi)
    const int a_kb  = (lane >> 4) << 4;
    const int b_row = (lane & 7) + ((lane >> 4) << 3);  // B x4: two 8-row n-tiles
    const int b_kb  = ((lane >> 3) & 1) << 4;

    if (tid < 64)
        ((float2*)(smem + SM_BIAS))[tid] = ((const float2*)(bias + n0))[tid];

    float acc[4][4][4];
    #pragma unroll
    for (int i = 0; i < 4; i++)
        #pragma unroll
        for (int j = 0; j < 4; j++)
            #pragma unroll
            for (int q = 0; q < 4; q++) acc[i][j][q] = 0.f;

    const float* aP = x + (size_t)m0 * K_DIM;
    const float* bP = g_wfull + (size_t)n0 * K_DIM;

    auto load_chunk = [&](int kc) {
        const uint32_t base = sb + SM_TILES + (uint32_t)(kc % STAGES) * STAGE_BYTES;
        const int k0 = kc * 32;
        #pragma unroll
        for (int j = 0; j < 4; j++) {       // A: 128 rows x 8 x 16B = 1024 ops
            int i = j * THREADS + tid, row = i >> 3, c = i & 7;
            cp16(base + A_OFF + swz((uint32_t)(row * 128 + c * 16)),
                 aP + (size_t)row * K_DIM + k0 + c * 4);
        }
        #pragma unroll
        for (int j = 0; j < 4; j++) {       // B: 128 rows x 8 x 16B = 1024 ops
            int i = j * THREADS + tid, row = i >> 3, c = i & 7;
            cp16(base + B_OFF + swz((uint32_t)(row * 128 + c * 16)),
                 bP + (size_t)row * K_DIM + k0 + c * 4);
        }
    };

    load_chunk(0); asm volatile("cp.async.commit_group;" ::: "memory");
    load_chunk(1); asm volatile("cp.async.commit_group;" ::: "memory");

    #pragma unroll 1
    for (int kc = 0; kc < CHUNKS; kc++) {
        asm volatile("cp.async.wait_group 1;" ::: "memory");
        __syncthreads();   // publishes chunk kc; orders compute(kc-1) before overwrite below
        if (kc + 2 < CHUNKS) load_chunk(kc + 2);
        asm volatile("cp.async.commit_group;" ::: "memory");

        const uint32_t sA = sb + SM_TILES + (uint32_t)(kc % STAGES) * STAGE_BYTES + A_OFF;
        const uint32_t sB = sA + B_OFF;
        #pragma unroll
        for (int ks = 0; ks < 4; ks++) {
            const int kbyte = ks * 32;
            uint32_t af[4][4], bf[2][4];
            #pragma unroll
            for (int mi = 0; mi < 4; mi++)
                ldsm4(af[mi], sA + swz((uint32_t)((wm + mi * 16 + a_row) * 128 + kbyte + a_kb)));
            #pragma unroll
            for (int np = 0; np < 2; np++)   // covers n-tiles 2*np, 2*np+1
                ldsm4(bf[np], sB + swz((uint32_t)((wn + np * 16 + b_row) * 128 + kbyte + b_kb)));
            #pragma unroll
            for (int mi = 0; mi < 4; mi++)
                #pragma unroll
                for (int np = 0; np < 2; np++) {
                    mma8(acc[mi][2 * np],     af[mi], &bf[np][0]);
                    mma8(acc[mi][2 * np + 1], af[mi], &bf[np][2]);
                }
        }
    }

    // epilogue: bias + store
    const float* bs = (const float*)(smem + SM_BIAS);
    #pragma unroll
    for (int mi = 0; mi < 4; mi++) {
        const int r0 = m0 + wm + mi * 16 + g;
        #pragma unroll
        for (int ni = 0; ni < 4; ni++) {
            const int col = wn + ni * 8 + 2 * t;
            float2 v0, v1;
            v0.x = acc[mi][ni][0] + bs[col];
            v0.y = acc[mi][ni][1] + bs[col + 1];
            v1.x = acc[mi][ni][2] + bs[col];
            v1.y = acc[mi][ni][3] + bs[col + 1];
            *(float2*)(out + (size_t)r0 * N_DIM + n0 + col) = v0;
            *(float2*)(out + (size_t)(r0 + 8) * N_DIM + n0 + col) = v1;
        }
    }
}

extern "C" void kernel_launch(void* const* d_in, const int* in_sizes, int n_in,
                              void* d_out, int out_size) {
    (void)in_sizes; (void)n_in; (void)out_size;
    const float* x    = (const float*)d_in[0];
    const float* w    = (const float*)d_in[1];
    const float* bias = (const float*)d_in[2];
    const int*   rn   = (const int*)d_in[3];
    float* out = (float*)d_out;

    gather_w<<<(N_DIM * K_DIM / 4) / 256, 256>>>(w, rn);

    cudaFuncSetAttribute(ssl_gemm, cudaFuncAttributeMaxDynamicSharedMemorySize, SMEM_TOTAL);
    ssl_gemm<<<dim3(N_DIM / NT, 8192 / MT), THREADS, SMEM_TOTAL>>>(x, bias, out);
}

// round 14
// speedup vs baseline: 1.7121x; 1.0041x over previous
#include <cuda_runtime.h>
#include <cstdint>

#define MT 128
#define NT 128
#define K_DIM 8192
#define N_DIM 512
#define CHUNKS (K_DIM / 32)
#define THREADS 256
#define STAGES 3

#define SM_BIAS   0
#define SM_TILES  1024
#define A_OFF     0
#define B_OFF     (MT * 128)                 // 16384
#define STAGE_BYTES ((MT + NT) * 128)        // 32768
#define SMEM_TOTAL (SM_TILES + STAGES * STAGE_BYTES)  // 99328 -> 2 CTAs/SM

// pre-gathered, tf32-rounded virtual weight [512][8192]
__device__ float g_wfull[(size_t)N_DIM * K_DIM];

// ---------------- helpers ----------------
__device__ __forceinline__ uint32_t smem_u32(const void* p) {
    uint32_t a;
    asm("{ .reg .u64 t; cvta.to.shared.u64 t, %1; cvt.u32.u64 %0, t; }" : "=r"(a) : "l"(p));
    return a;
}
__device__ __forceinline__ uint32_t swz(uint32_t o) { return o ^ ((o >> 3) & 0x70); }

__device__ __forceinline__ void cp16(uint32_t dst, const void* src) {
    asm volatile("cp.async.cg.shared.global [%0], [%1], 16;" :: "r"(dst), "l"(src) : "memory");
}

// ldmatrix x4: four 8x8 b16 tiles; tf32-compatible (bit-pattern agnostic)
__device__ __forceinline__ void ldsm4(uint32_t* r, uint32_t addr) {
    asm volatile("ldmatrix.sync.aligned.m8n8.x4.shared.b16 {%0,%1,%2,%3}, [%4];"
                 : "=r"(r[0]), "=r"(r[1]), "=r"(r[2]), "=r"(r[3]) : "r"(addr));
}

__device__ __forceinline__ void mma8(float* c, const uint32_t* a, const uint32_t* b) {
    asm volatile(
        "mma.sync.aligned.m16n8k8.row.col.f32.tf32.tf32.f32 "
        "{%0,%1,%2,%3}, {%4,%5,%6,%7}, {%8,%9}, {%0,%1,%2,%3};"
        : "+f"(c[0]), "+f"(c[1]), "+f"(c[2]), "+f"(c[3])
        : "r"(a[0]), "r"(a[1]), "r"(a[2]), "r"(a[3]), "r"(b[0]), "r"(b[1]));
}

// ---------------- pre-gather: w_full[n][k] = rna_tf32(weight[n][h(n/32,k/32)*32 + k%32])
__global__ void gather_w(const float* __restrict__ w, const int* __restrict__ rn) {
    const uint32_t r0 = (uint32_t)rn[0], r1 = (uint32_t)rn[1],
                   r2 = (uint32_t)rn[2], r3 = (uint32_t)rn[3];
    int gid = blockIdx.x * 256 + threadIdx.x;     // [0, 512*8192/4)
    int n = gid >> 11;                            // / 2048
    int k = (gid & 2047) << 2;
    uint32_t kb = (uint32_t)(k >> 5), nb = (uint32_t)(n >> 5);
    uint32_t h = ((kb * r0 + nb * r1 + r2) ^ r3) % 32u;
    const float4 v = *(const float4*)(w + n * 1024 + h * 32u + (k & 31));
    uint4 o;
    asm("cvt.rna.tf32.f32 %0, %1;" : "=r"(o.x) : "f"(v.x));
    asm("cvt.rna.tf32.f32 %0, %1;" : "=r"(o.y) : "f"(v.y));
    asm("cvt.rna.tf32.f32 %0, %1;" : "=r"(o.z) : "f"(v.z));
    asm("cvt.rna.tf32.f32 %0, %1;" : "=r"(o.w) : "f"(v.w));
    *(uint4*)(g_wfull + (size_t)n * K_DIM + k) = o;
}

// ---------------- main GEMM ----------------
__global__ void __launch_bounds__(THREADS, 2)
ssl_gemm(const float* __restrict__ x, const float* __restrict__ bias, float* __restrict__ out) {
    extern __shared__ char smem[];
    const uint32_t sb = smem_u32(smem);
    const int tid = threadIdx.x;
    const int lane = tid & 31, wid = tid >> 5;
    const int wm = (wid & 1) * 64;       // 2 warp-rows of 64
    const int wn = (wid >> 1) * 32;      // 4 warp-cols of 32
    const int g = lane >> 2, t = lane & 3;
    const int m0 = blockIdx.y * MT, n0 = blockIdx.x * NT;

    // ldmatrix per-thread selectors
    const int a_row = lane & 15;                 // A x4: 16 rows x 32B (k-lo/k-hi)
    const int a_kb  = (lane >> 4) << 4;
    const int b_row = (lane & 7) + ((lane >> 4) << 3);  // B x4: two 8-row n-tiles
    const int b_kb  = ((lane >> 3) & 1) << 4;

    if (tid < 64)
        ((float2*)(smem + SM_BIAS))[tid] = ((const float2*)(bias + n0))[tid];

    float acc[4][4][4];
    #pragma unroll
    for (int i = 0; i < 4; i++)
        #pragma unroll
        for (int j = 0; j < 4; j++)
            #pragma unroll
            for (int q = 0; q < 4; q++) acc[i][j][q] = 0.f;

    const float* aP = x + (size_t)m0 * K_DIM;
    const float* bP = g_wfull + (size_t)n0 * K_DIM;

    auto load_chunk = [&](int kc) {
        const uint32_t base = sb + SM_TILES + (uint32_t)(kc % STAGES) * STAGE_BYTES;
        const int k0 = kc * 32;
        #pragma unroll
        for (int j = 0; j < 4; j++) {       // A: 128 rows x 8 x 16B = 1024 ops
            int i = j * THREADS + tid, row = i >> 3, c = i & 7;
            cp16(base + A_OFF + swz((uint32_t)(row * 128 + c * 16)),
                 aP + (size_t)row * K_DIM + k0 + c * 4);
        }
        #pragma unroll
        for (int j = 0; j < 4; j++) {       // B: 128 rows x 8 x 16B = 1024 ops
            int i = j * THREADS + tid, row = i >> 3, c = i & 7;
            cp16(base + B_OFF + swz((uint32_t)(row * 128 + c * 16)),
                 bP + (size_t)row * K_DIM + k0 + c * 4);
        }
    };

    load_chunk(0); asm volatile("cp.async.commit_group;" ::: "memory");
    load_chunk(1); asm volatile("cp.async.commit_group;" ::: "memory");

    #pragma unroll 1
    for (int kc = 0; kc < CHUNKS; kc++) {
        asm volatile("cp.async.wait_group 1;" ::: "memory");
        __syncthreads();   // publishes chunk kc; orders compute(kc-1) before overwrite below
        if (kc + 2 < CHUNKS) load_chunk(kc + 2);
        asm volatile("cp.async.commit_group;" ::: "memory");

        const uint32_t sA = sb + SM_TILES + (uint32_t)(kc % STAGES) * STAGE_BYTES + A_OFF;
        const uint32_t sB = sA + B_OFF;
        #pragma unroll
        for (int ks2 = 0; ks2 < 4; ks2++) {
            // per-warp ks skew: decorrelates the LDSM burst vs MMA burst phases
            // across the 16 warps on an SM (sum over ks is order-independent)
            const int ks = (ks2 + wid) & 3;
            const int kbyte = ks * 32;
            uint32_t af[4][4], bf[2][4];
            #pragma unroll
            for (int mi = 0; mi < 4; mi++)
                ldsm4(af[mi], sA + swz((uint32_t)((wm + mi * 16 + a_row) * 128 + kbyte + a_kb)));
            #pragma unroll
            for (int np = 0; np < 2; np++)   // covers n-tiles 2*np, 2*np+1
                ldsm4(bf[np], sB + swz((uint32_t)((wn + np * 16 + b_row) * 128 + kbyte + b_kb)));
            #pragma unroll
            for (int mi = 0; mi < 4; mi++)
                #pragma unroll
                for (int np = 0; np < 2; np++) {
                    mma8(acc[mi][2 * np],     af[mi], &bf[np][0]);
                    mma8(acc[mi][2 * np + 1], af[mi], &bf[np][2]);
                }
        }
    }

    // epilogue: bias + store
    const float* bs = (const float*)(smem + SM_BIAS);
    #pragma unroll
    for (int mi = 0; mi < 4; mi++) {
        const int r0 = m0 + wm + mi * 16 + g;
        #pragma unroll
        for (int ni = 0; ni < 4; ni++) {
            const int col = wn + ni * 8 + 2 * t;
            float2 v0, v1;
            v0.x = acc[mi][ni][0] + bs[col];
            v0.y = acc[mi][ni][1] + bs[col + 1];
            v1.x = acc[mi][ni][2] + bs[col];
            v1.y = acc[mi][ni][3] + bs[col + 1];
            *(float2*)(out + (size_t)r0 * N_DIM + n0 + col) = v0;
            *(float2*)(out + (size_t)(r0 + 8) * N_DIM + n0 + col) = v1;
        }
    }
}

extern "C" void kernel_launch(void* const* d_in, const int* in_sizes, int n_in,
                              void* d_out, int out_size) {
    (void)in_sizes; (void)n_in; (void)out_size;
    const float* x    = (const float*)d_in[0];
    const float* w    = (const float*)d_in[1];
    const float* bias = (const float*)d_in[2];
    const int*   rn   = (const int*)d_in[3];
    float* out = (float*)d_out;

    gather_w<<<(N_DIM * K_DIM / 4) / 256, 256>>>(w, rn);

    cudaFuncSetAttribute(ssl_gemm, cudaFuncAttributeMaxDynamicSharedMemorySize, SMEM_TOTAL);
    ssl_gemm<<<dim3(N_DIM / NT, 8192 / MT), THREADS, SMEM_TOTAL>>>(x, bias, out);
}

// round 15
// speedup vs baseline: 2.4636x; 1.4389x over previous
#include <cuda_runtime.h>
#include <cuda_fp16.h>
#include <cstdint>

#define MT 128
#define NT 128
#define K_DIM 8192
#define N_DIM 512
#define M_DIM 8192
#define CHUNKS (K_DIM / 64)       // 64 k-elements (128B of fp16) per chunk
#define THREADS 256
#define STAGES 3

#define SM_BIAS   0
#define SM_TILES  1024
#define A_OFF     0
#define B_OFF     (MT * 128)                 // 16384
#define STAGE_BYTES ((MT + NT) * 128)        // 32768
#define SMEM_TOTAL (SM_TILES + STAGES * STAGE_BYTES)  // 99328 -> 2 CTAs/SM

// fp16 copies: x (128 MB) and hashed-gathered weight (8 MB)
__device__ __half g_xh[(size_t)M_DIM * K_DIM];
__device__ __half g_wh[(size_t)N_DIM * K_DIM];

// ---------------- helpers ----------------
__device__ __forceinline__ uint32_t smem_u32(const void* p) {
    uint32_t a;
    asm("{ .reg .u64 t; cvta.to.shared.u64 t, %1; cvt.u32.u64 %0, t; }" : "=r"(a) : "l"(p));
    return a;
}
__device__ __forceinline__ uint32_t swz(uint32_t o) { return o ^ ((o >> 3) & 0x70); }

__device__ __forceinline__ void cp16(uint32_t dst, const void* src) {
    asm volatile("cp.async.cg.shared.global [%0], [%1], 16;" :: "r"(dst), "l"(src) : "memory");
}

__device__ __forceinline__ void ldsm4(uint32_t* r, uint32_t addr) {
    asm volatile("ldmatrix.sync.aligned.m8n8.x4.shared.b16 {%0,%1,%2,%3}, [%4];"
                 : "=r"(r[0]), "=r"(r[1]), "=r"(r[2]), "=r"(r[3]) : "r"(addr));
}

// fp16 HMMA, fp32 accumulate: 2048 MACs/instr (2x tf32 k8 at same issue rate)
__device__ __forceinline__ void mma16(float* c, const uint32_t* a, const uint32_t* b) {
    asm volatile(
        "mma.sync.aligned.m16n8k16.row.col.f32.f16.f16.f32 "
        "{%0,%1,%2,%3}, {%4,%5,%6,%7}, {%8,%9}, {%0,%1,%2,%3};"
        : "+f"(c[0]), "+f"(c[1]), "+f"(c[2]), "+f"(c[3])
        : "r"(a[0]), "r"(a[1]), "r"(a[2]), "r"(a[3]), "r"(b[0]), "r"(b[1]));
}

// ---------------- prekernel 1: x -> fp16 ----------------
__global__ void conv_x(const float* __restrict__ x) {
    size_t i = ((size_t)blockIdx.x * 256 + threadIdx.x) * 4;
    const float4 v = *(const float4*)(x + i);
    __half2 h0 = __floats2half2_rn(v.x, v.y);
    __half2 h1 = __floats2half2_rn(v.z, v.w);
    uint2 o;
    o.x = *(uint32_t*)&h0;
    o.y = *(uint32_t*)&h1;
    *(uint2*)(g_xh + i) = o;
}

// ---------------- prekernel 2: hashed gather of w -> fp16 ----------------
__global__ void gather_w(const float* __restrict__ w, const int* __restrict__ rn) {
    const uint32_t r0 = (uint32_t)rn[0], r1 = (uint32_t)rn[1],
                   r2 = (uint32_t)rn[2], r3 = (uint32_t)rn[3];
    int gid = blockIdx.x * 256 + threadIdx.x;     // [0, 512*8192/4)
    int n = gid >> 11;                            // / 2048
    int k = (gid & 2047) << 2;
    uint32_t kb = (uint32_t)(k >> 5), nb = (uint32_t)(n >> 5);
    uint32_t h = ((kb * r0 + nb * r1 + r2) ^ r3) % 32u;
    const float4 v = *(const float4*)(w + n * 1024 + h * 32u + (k & 31));
    __half2 h0 = __floats2half2_rn(v.x, v.y);
    __half2 h1 = __floats2half2_rn(v.z, v.w);
    uint2 o;
    o.x = *(uint32_t*)&h0;
    o.y = *(uint32_t*)&h1;
    *(uint2*)(g_wh + (size_t)n * K_DIM + k) = o;
}

// ---------------- main GEMM (fp16 in, fp32 accum) ----------------
__global__ void __launch_bounds__(THREADS, 2)
ssl_gemm(const float* __restrict__ bias, float* __restrict__ out) {
    extern __shared__ char smem[];
    const uint32_t sb = smem_u32(smem);
    const int tid = threadIdx.x;
    const int lane = tid & 31, wid = tid >> 5;
    const int wm = (wid & 1) * 64;       // 2 warp-rows of 64
    const int wn = (wid >> 1) * 32;      // 4 warp-cols of 32
    const int g = lane >> 2, t = lane & 3;
    const int m0 = blockIdx.y * MT, n0 = blockIdx.x * NT;

    // ldmatrix per-thread selectors (byte layout identical to tf32-k8 version:
    // one k-step = 32 bytes, A x4 = 16 rows x 32B, B x4 = two 8-row n-tiles x 32B)
    const int a_row = lane & 15;
    const int a_kb  = (lane >> 4) << 4;
    const int b_row = (lane & 7) + ((lane >> 4) << 3);
    const int b_kb  = ((lane >> 3) & 1) << 4;

    if (tid < 64)
        ((float2*)(smem + SM_BIAS))[tid] = ((const float2*)(bias + n0))[tid];

    float acc[4][4][4];
    #pragma unroll
    for (int i = 0; i < 4; i++)
        #pragma unroll
        for (int j = 0; j < 4; j++)
            #pragma unroll
            for (int q = 0; q < 4; q++) acc[i][j][q] = 0.f;

    const __half* aP = g_xh + (size_t)m0 * K_DIM;
    const __half* bP = g_wh + (size_t)n0 * K_DIM;

    auto load_chunk = [&](int kc) {
        const uint32_t base = sb + SM_TILES + (uint32_t)(kc % STAGES) * STAGE_BYTES;
        const int k0 = kc * 64;                    // 64 halves per chunk row
        #pragma unroll
        for (int j = 0; j < 4; j++) {              // A: 128 rows x 8 x 16B
            int i = j * THREADS + tid, row = i >> 3, c = i & 7;
            cp16(base + A_OFF + swz((uint32_t)(row * 128 + c * 16)),
                 aP + (size_t)row * K_DIM + k0 + c * 8);
        }
        #pragma unroll
        for (int j = 0; j < 4; j++) {              // B: 128 rows x 8 x 16B
            int i = j * THREADS + tid, row = i >> 3, c = i & 7;
            cp16(base + B_OFF + swz((uint32_t)(row * 128 + c * 16)),
                 bP + (size_t)row * K_DIM + k0 + c * 8);
        }
    };

    load_chunk(0); asm volatile("cp.async.commit_group;" ::: "memory");
    load_chunk(1); asm volatile("cp.async.commit_group;" ::: "memory");

    #pragma unroll 1
    for (int kc = 0; kc < CHUNKS; kc++) {
        asm volatile("cp.async.wait_group 1;" ::: "memory");
        __syncthreads();   // publishes chunk kc; orders compute(kc-1) before overwrite below
        if (kc + 2 < CHUNKS) load_chunk(kc + 2);
        asm volatile("cp.async.commit_group;" ::: "memory");

        const uint32_t sA = sb + SM_TILES + (uint32_t)(kc % STAGES) * STAGE_BYTES + A_OFF;
        const uint32_t sB = sA + B_OFF;
        #pragma unroll
        for (int ks = 0; ks < 4; ks++) {           // 4 x k16 steps = 64 k per chunk
            const int kbyte = ks * 32;
            uint32_t af[4][4], bf[2][4];
            #pragma unroll
            for (int mi = 0; mi < 4; mi++)
                ldsm4(af[mi], sA + swz((uint32_t)((wm + mi * 16 + a_row) * 128 + kbyte + a_kb)));
            #pragma unroll
            for (int np = 0; np < 2; np++)         // covers n-tiles 2*np, 2*np+1
                ldsm4(bf[np], sB + swz((uint32_t)((wn + np * 16 + b_row) * 128 + kbyte + b_kb)));
            #pragma unroll
            for (int mi = 0; mi < 4; mi++)
                #pragma unroll
                for (int np = 0; np < 2; np++) {
                    mma16(acc[mi][2 * np],     af[mi], &bf[np][0]);
                    mma16(acc[mi][2 * np + 1], af[mi], &bf[np][2]);
                }
        }
    }

    // epilogue: bias + store
    const float* bs = (const float*)(smem + SM_BIAS);
    #pragma unroll
    for (int mi = 0; mi < 4; mi++) {
        const int r0 = m0 + wm + mi * 16 + g;
        #pragma unroll
        for (int ni = 0; ni < 4; ni++) {
            const int col = wn + ni * 8 + 2 * t;
            float2 v0, v1;
            v0.x = acc[mi][ni][0] + bs[col];
            v0.y = acc[mi][ni][1] + bs[col + 1];
            v1.x = acc[mi][ni][2] + bs[col];
            v1.y = acc[mi][ni][3] + bs[col + 1];
            *(float2*)(out + (size_t)r0 * N_DIM + n0 + col) = v0;
            *(float2*)(out + (size_t)(r0 + 8) * N_DIM + n0 + col) = v1;
        }
    }
}

extern "C" void kernel_launch(void* const* d_in, const int* in_sizes, int n_in,
                              void* d_out, int out_size) {
    (void)in_sizes; (void)n_in; (void)out_size;
    const float* x    = (const float*)d_in[0];
    const float* w    = (const float*)d_in[1];
    const float* bias = (const float*)d_in[2];
    const int*   rn   = (const int*)d_in[3];
    float* out = (float*)d_out;

    conv_x<<<(int)(((size_t)M_DIM * K_DIM / 4) / 256), 256>>>(x);
    gather_w<<<(N_DIM * K_DIM / 4) / 256, 256>>>(w, rn);

    cudaFuncSetAttribute(ssl_gemm, cudaFuncAttributeMaxDynamicSharedMemorySize, SMEM_TOTAL);
    ssl_gemm<<<dim3(N_DIM / NT, M_DIM / MT), THREADS, SMEM_TOTAL>>>(bias, out);
}